// round 7
// baseline (speedup 1.0000x reference)
#include <cuda_runtime.h>
#include <cstdint>

#define BB 8
#define NN 2048
#define IND 256
#define OUTD 128
#define ROWS (BB * NN)   // 16384
#define NEG_SLOPE 0.2f

// Scratch (device globals — no allocation allowed)
__device__ float g_Wh[ROWS * OUTD];   // 8 MB, tf32-rounded values
__device__ float g_E1[ROWS];          // exp(f1)
__device__ float g_G1[ROWS];          // exp(0.2*f1)
__device__ float g_E2[ROWS];          // exp(f2)
__device__ float g_G2[ROWS];          // exp(0.2*f2)

__device__ __forceinline__ uint32_t f2tf32(float x) {
    uint32_t r;
    asm("cvt.rna.tf32.f32 %0, %1;" : "=r"(r) : "f"(x));
    return r;
}

__device__ __forceinline__ void cp_async16(void* dst_smem, const void* src) {
    uint32_t d = (uint32_t)__cvta_generic_to_shared(dst_smem);
    asm volatile("cp.async.cg.shared.global [%0], [%1], 16;\n"
                 :: "r"(d), "l"(src));
}
#define CP_COMMIT() asm volatile("cp.async.commit_group;\n" ::: "memory")
#define CP_WAIT0()  asm volatile("cp.async.wait_group 0;\n" ::: "memory")

// ---------------------------------------------------------------------------
// Kernel 1: Wh = h @ W  (16384x256 @ 256x128).
// Epilogue: f1 = Wh·a1, f2 = Wh·a2 in full precision, then store the FOUR
// exponential factors (exp(f), exp(0.2 f)) so k2's inner loop needs NO exp:
//   exp(leaky(fi+fj)) == max(E1[i]*E2[j], G1[i]*G2[j])
// (for x>=0: e^x >= e^{0.2x}; for x<0: e^{0.2x} > e^x — max picks right branch,
//  and the function is continuous at x=0 so boundary rounding is harmless).
// Wh is stored tf32-rounded (rna) so k2's B operand needs no conversion.
// ---------------------------------------------------------------------------
__global__ __launch_bounds__(256) void k1_gemm_wh(
    const float* __restrict__ h, const float* __restrict__ W,
    const float* __restrict__ a)
{
    __shared__ float hs[64][32];
    __shared__ float Ws[32][128];

    const int t  = threadIdx.x;
    const int ty = t >> 5;
    const int tx = t & 31;
    const int row0 = blockIdx.x * 64;

    float acc[8][4];
    #pragma unroll
    for (int i = 0; i < 8; i++)
        #pragma unroll
        for (int j = 0; j < 4; j++) acc[i][j] = 0.f;

    float a1v[4], a2v[4];
    #pragma unroll
    for (int cc = 0; cc < 4; cc++) {
        a1v[cc] = a[tx * 4 + cc];
        a2v[cc] = a[OUTD + tx * 4 + cc];
    }

    const int lr = t >> 3;
    const int lc = (t & 7) * 4;

    for (int k0 = 0; k0 < IND; k0 += 32) {
        *(float4*)&hs[lr][lc] =
            *(const float4*)&h[(size_t)(row0 + lr) * IND + k0 + lc];
        *(float4*)&hs[lr + 32][lc] =
            *(const float4*)&h[(size_t)(row0 + lr + 32) * IND + k0 + lc];
        #pragma unroll
        for (int p = 0; p < 4; p++) {
            int idx = t * 4 + p * 1024;
            int wr = idx >> 7, wc = idx & 127;
            *(float4*)&Ws[wr][wc] = *(const float4*)&W[(size_t)(k0 + wr) * OUTD + wc];
        }
        __syncthreads();

        #pragma unroll 8
        for (int kk = 0; kk < 32; kk++) {
            float4 wq = *(const float4*)&Ws[kk][tx * 4];
            #pragma unroll
            for (int rr = 0; rr < 8; rr++) {
                float hv = hs[ty * 8 + rr][kk];
                acc[rr][0] += hv * wq.x;
                acc[rr][1] += hv * wq.y;
                acc[rr][2] += hv * wq.z;
                acc[rr][3] += hv * wq.w;
            }
        }
        __syncthreads();
    }

    #pragma unroll
    for (int rr = 0; rr < 8; rr++) {
        const int r = row0 + ty * 8 + rr;
        float4 o;
        o.x = __uint_as_float(f2tf32(acc[rr][0]));
        o.y = __uint_as_float(f2tf32(acc[rr][1]));
        o.z = __uint_as_float(f2tf32(acc[rr][2]));
        o.w = __uint_as_float(f2tf32(acc[rr][3]));
        *(float4*)&g_Wh[(size_t)r * OUTD + tx * 4] = o;

        float s1 = acc[rr][0] * a1v[0] + acc[rr][1] * a1v[1] +
                   acc[rr][2] * a1v[2] + acc[rr][3] * a1v[3];
        float s2 = acc[rr][0] * a2v[0] + acc[rr][1] * a2v[1] +
                   acc[rr][2] * a2v[2] + acc[rr][3] * a2v[3];
        #pragma unroll
        for (int off = 16; off; off >>= 1) {
            s1 += __shfl_xor_sync(0xFFFFFFFFu, s1, off);
            s2 += __shfl_xor_sync(0xFFFFFFFFu, s2, off);
        }
        if (tx == 0) {
            g_E1[r] = expf(s1);
            g_G1[r] = expf(NEG_SLOPE * s1);
            g_E2[r] = expf(s2);
            g_G2[r] = expf(NEG_SLOPE * s2);
        }
    }
}

// ---------------------------------------------------------------------------
// Kernel 2: fused masked-softmax attention aggregate, tf32 mma.sync,
// cp.async double-buffered Wh/E2/G2 tiles, exp-free weight computation,
// m32n32 warp tiles (2 m-warps x 4 n-warps).
//
// per iter t (buf idx = t&1):
//   wait cp.async; sync#1          (buffers ready; MMA(t-1) done)
//   weights(t): w = max(Efi*Efj, Gfi*Gfj) * adj  -> wts (tf32), Z += w
//   sync#2
//   issue cp.async for tile t+1    (overlaps MMA)
//   MMA(t): acc += wts(64x64) @ WhS[idx](64x128)
// ---------------------------------------------------------------------------
#define WHS_STRIDE 136
#define WTS_STRIDE 68
#define SM_WHS  0                          // [2][64][136]
#define SM_WTS  (2 * 64 * WHS_STRIDE)      // [64][68]
#define SM_EJS  (SM_WTS + 64 * WTS_STRIDE) // [2][64]
#define SM_GJS  (SM_EJS + 128)             // [2][64]
#define SM_ZS   (SM_GJS + 128)             // [64]
#define SM_TOT  (SM_ZS + 64)
#define SM_BYTES (SM_TOT * 4)

__device__ __forceinline__ void mma_tf32(float* d, const uint32_t* a,
                                         uint32_t b0, uint32_t b1) {
    asm volatile(
        "mma.sync.aligned.m16n8k8.row.col.f32.tf32.tf32.f32 "
        "{%0,%1,%2,%3}, {%4,%5,%6,%7}, {%8,%9}, {%0,%1,%2,%3};\n"
        : "+f"(d[0]), "+f"(d[1]), "+f"(d[2]), "+f"(d[3])
        : "r"(a[0]), "r"(a[1]), "r"(a[2]), "r"(a[3]), "r"(b0), "r"(b1));
}

__global__ __launch_bounds__(256, 2) void k2_attn(
    const float* __restrict__ adj, float* __restrict__ out)
{
    extern __shared__ float sm[];
    float* WhS = sm + SM_WHS;    // [2][64][136] tf32 bits (from k1)
    float* wts = sm + SM_WTS;    // [64][68] tf32 bits
    float* ejs = sm + SM_EJS;    // [2][64] exp(f2)
    float* gjs = sm + SM_GJS;    // [2][64] exp(0.2 f2)
    float* Zs  = sm + SM_ZS;     // [64]
    const uint32_t* wtsu = (const uint32_t*)wts;

    const int t    = threadIdx.x;
    const int wid  = t >> 5;
    const int lane = t & 31;
    const int gid  = lane >> 2;
    const int tig  = lane & 3;
    const int b    = blockIdx.y;
    const int i0   = blockIdx.x * 64;

    // m32n32 warp tiles: 2 warps on M (32 rows each), 4 on N (32 cols each)
    const int m_warp = (wid & 1) * 32;
    const int n_warp = (wid >> 1) * 32;

    const int wr  = t >> 2;          // weight row 0..63
    const int wc0 = (t & 3) * 16;    // weight col base

    if (t < 64) Zs[t] = 0.f;

    const float Efi = g_E1[(size_t)b * NN + i0 + wr];
    const float Gfi = g_G1[(size_t)b * NN + i0 + wr];
    const float* Whb = g_Wh + (size_t)b * NN * OUTD;
    const float* E2b = g_E2 + (size_t)b * NN;
    const float* G2b = g_G2 + (size_t)b * NN;

    // ---- prologue: async-fill buffer 0 with tile 0
    {
        #pragma unroll
        for (int p = 0; p < 8; p++) {
            int c = t + p * 256;              // 0..2047
            int r = c >> 5, c16 = c & 31;
            cp_async16(&WhS[r * WHS_STRIDE + c16 * 4],
                       &Whb[(size_t)r * OUTD + c16 * 4]);
        }
        if (t < 16)      cp_async16(&ejs[t * 4],        &E2b[t * 4]);
        else if (t < 32) cp_async16(&gjs[(t - 16) * 4], &G2b[(t - 16) * 4]);
        CP_COMMIT();
    }

    float acc[2][4][4];
    #pragma unroll
    for (int u = 0; u < 2; u++)
        #pragma unroll
        for (int v = 0; v < 4; v++)
            #pragma unroll
            for (int j = 0; j < 4; j++) acc[u][v][j] = 0.f;

    float Zpart = 0.f;

    for (int tt = 0; tt < NN / 64; tt++) {
        const int idx = tt & 1;
        const int j0 = tt * 64;
        const uint32_t* WhBufu =
            (const uint32_t*)(WhS + idx * 64 * WHS_STRIDE);
        const float* ejBuf = ejs + idx * 64;
        const float* gjBuf = gjs + idx * 64;

        CP_WAIT0();
        __syncthreads();          // sync#1: buffers ready, MMA(t-1) done

        // ---- weight tile: 16 entries/thread, NO exp, branchless
        {
            const float* adjrow = adj + (size_t)(i0 + wr) * NN + j0 + wc0;
            #pragma unroll
            for (int q = 0; q < 4; q++) {
                float4 av = *(const float4*)&adjrow[q * 4];
                float4 ej = *(const float4*)&ejBuf[wc0 + q * 4];
                float4 gj = *(const float4*)&gjBuf[wc0 + q * 4];
                float am[4] = {av.x, av.y, av.z, av.w};
                float ev[4] = {ej.x, ej.y, ej.z, ej.w};
                float gv[4] = {gj.x, gj.y, gj.z, gj.w};
                uint32_t wb[4];
                #pragma unroll
                for (int s = 0; s < 4; s++) {
                    float w = fmaxf(Efi * ev[s], Gfi * gv[s]) * am[s];
                    uint32_t wt = f2tf32(w);
                    wb[s] = wt;
                    Zpart += __uint_as_float(wt);
                }
                *(uint4*)&wts[wr * WTS_STRIDE + wc0 + q * 4] =
                    make_uint4(wb[0], wb[1], wb[2], wb[3]);
            }
        }
        __syncthreads();          // sync#2: wts complete

        // ---- prefetch next tile (overlaps MMA below)
        if (tt + 1 < NN / 64) {
            const int j1 = j0 + 64;
            float* whdst = WhS + (idx ^ 1) * 64 * WHS_STRIDE;
            #pragma unroll
            for (int p = 0; p < 8; p++) {
                int c = t + p * 256;
                int r = c >> 5, c16 = c & 31;
                cp_async16(&whdst[r * WHS_STRIDE + c16 * 4],
                           &Whb[(size_t)(j1 + r) * OUTD + c16 * 4]);
            }
            if (t < 16)
                cp_async16(&ejs[(idx ^ 1) * 64 + t * 4], &E2b[j1 + t * 4]);
            else if (t < 32)
                cp_async16(&gjs[(idx ^ 1) * 64 + (t - 16) * 4],
                           &G2b[j1 + (t - 16) * 4]);
            CP_COMMIT();
        }

        // ---- tensor-core accumulate: acc += wts(64x64) @ WhBuf(64x128)
        #pragma unroll
        for (int k0 = 0; k0 < 64; k0 += 8) {
            uint32_t afrag[2][4];
            #pragma unroll
            for (int u = 0; u < 2; u++) {
                int base = (m_warp + u * 16 + gid) * WTS_STRIDE + k0 + tig;
                afrag[u][0] = wtsu[base];
                afrag[u][1] = wtsu[base + 8 * WTS_STRIDE];
                afrag[u][2] = wtsu[base + 4];
                afrag[u][3] = wtsu[base + 8 * WTS_STRIDE + 4];
            }
            #pragma unroll
            for (int v = 0; v < 4; v++) {
                int nb = n_warp + v * 8 + gid;
                uint32_t b0 = WhBufu[(k0 + tig) * WHS_STRIDE + nb];
                uint32_t b1 = WhBufu[(k0 + tig + 4) * WHS_STRIDE + nb];
                mma_tf32(acc[0][v], afrag[0], b0, b1);
                mma_tf32(acc[1][v], afrag[1], b0, b1);
            }
        }
    }

    atomicAdd(&Zs[wr], Zpart);
    __syncthreads();

    // ---- epilogue: divide by Z, store
    #pragma unroll
    for (int u = 0; u < 2; u++) {
        const int row0e = m_warp + u * 16 + gid;
        const int row1e = row0e + 8;
        const float inv0 = 1.f / Zs[row0e];
        const float inv1 = 1.f / Zs[row1e];
        float* out0 = out + ((size_t)b * NN + i0 + row0e) * OUTD;
        float* out1 = out + ((size_t)b * NN + i0 + row1e) * OUTD;
        #pragma unroll
        for (int v = 0; v < 4; v++) {
            int col = n_warp + v * 8 + tig * 2;
            *(float2*)&out0[col] = make_float2(acc[u][v][0] * inv0,
                                               acc[u][v][1] * inv0);
            *(float2*)&out1[col] = make_float2(acc[u][v][2] * inv1,
                                               acc[u][v][3] * inv1);
        }
    }
}

// ---------------------------------------------------------------------------
extern "C" void kernel_launch(void* const* d_in, const int* in_sizes, int n_in,
                              void* d_out, int out_size)
{
    const float* h   = (const float*)d_in[0];   // (8, 2048, 256)
    const float* adj = (const float*)d_in[1];   // (2048, 2048)
    const float* W   = (const float*)d_in[2];   // (256, 128)
    const float* a   = (const float*)d_in[3];   // (256,)
    float* out = (float*)d_out;                 // (8, 2048, 128)

    k1_gemm_wh<<<ROWS / 64, 256>>>(h, W, a);

    cudaFuncSetAttribute(k2_attn, cudaFuncAttributeMaxDynamicSharedMemorySize,
                         SM_BYTES);
    k2_attn<<<dim3(NN / 64, BB), 256, SM_BYTES>>>(adj, out);
}

// round 8
// speedup vs baseline: 1.0082x; 1.0082x over previous
#include <cuda_runtime.h>
#include <cstdint>

#define BB 8
#define NN 2048
#define IND 256
#define OUTD 128
#define ROWS (BB * NN)   // 16384
#define NEG_SLOPE 0.2f

// Scratch (device globals — no allocation allowed)
__device__ float g_Wh[ROWS * OUTD];   // 8 MB, tf32-rounded values
__device__ float g_E1[ROWS];          // exp(f1)
__device__ float g_G1[ROWS];          // exp(0.2*f1)
__device__ float g_E2[ROWS];          // exp(f2)
__device__ float g_G2[ROWS];          // exp(0.2*f2)

__device__ __forceinline__ uint32_t f2tf32(float x) {
    uint32_t r;
    asm("cvt.rna.tf32.f32 %0, %1;" : "=r"(r) : "f"(x));
    return r;
}

__device__ __forceinline__ void cp_async16(void* dst_smem, const void* src) {
    uint32_t d = (uint32_t)__cvta_generic_to_shared(dst_smem);
    asm volatile("cp.async.cg.shared.global [%0], [%1], 16;\n"
                 :: "r"(d), "l"(src));
}
#define CP_COMMIT() asm volatile("cp.async.commit_group;\n" ::: "memory")
#define CP_WAIT0()  asm volatile("cp.async.wait_group 0;\n" ::: "memory")

// ---------------------------------------------------------------------------
// Kernel 1: Wh = h @ W  (16384x256 @ 256x128).
// Epilogue: f1 = Wh·a1, f2 = Wh·a2 in full precision, then store the FOUR
// exponential factors (exp(f), exp(0.2 f)) so k2's inner loop needs NO exp:
//   exp(leaky(fi+fj)) == max(E1[i]*E2[j], G1[i]*G2[j])
// (for x>=0: e^x >= e^{0.2x}; for x<0: e^{0.2x} > e^x — max picks right branch,
//  and the function is continuous at x=0 so boundary rounding is harmless).
// Wh is stored tf32-rounded (rna) so k2's B operand needs no conversion.
// ---------------------------------------------------------------------------
__global__ __launch_bounds__(256) void k1_gemm_wh(
    const float* __restrict__ h, const float* __restrict__ W,
    const float* __restrict__ a)
{
    __shared__ float hs[64][32];
    __shared__ float Ws[32][128];

    const int t  = threadIdx.x;
    const int ty = t >> 5;
    const int tx = t & 31;
    const int row0 = blockIdx.x * 64;

    float acc[8][4];
    #pragma unroll
    for (int i = 0; i < 8; i++)
        #pragma unroll
        for (int j = 0; j < 4; j++) acc[i][j] = 0.f;

    float a1v[4], a2v[4];
    #pragma unroll
    for (int cc = 0; cc < 4; cc++) {
        a1v[cc] = a[tx * 4 + cc];
        a2v[cc] = a[OUTD + tx * 4 + cc];
    }

    const int lr = t >> 3;
    const int lc = (t & 7) * 4;

    for (int k0 = 0; k0 < IND; k0 += 32) {
        *(float4*)&hs[lr][lc] =
            *(const float4*)&h[(size_t)(row0 + lr) * IND + k0 + lc];
        *(float4*)&hs[lr + 32][lc] =
            *(const float4*)&h[(size_t)(row0 + lr + 32) * IND + k0 + lc];
        #pragma unroll
        for (int p = 0; p < 4; p++) {
            int idx = t * 4 + p * 1024;
            int wr = idx >> 7, wc = idx & 127;
            *(float4*)&Ws[wr][wc] = *(const float4*)&W[(size_t)(k0 + wr) * OUTD + wc];
        }
        __syncthreads();

        #pragma unroll 8
        for (int kk = 0; kk < 32; kk++) {
            float4 wq = *(const float4*)&Ws[kk][tx * 4];
            #pragma unroll
            for (int rr = 0; rr < 8; rr++) {
                float hv = hs[ty * 8 + rr][kk];
                acc[rr][0] += hv * wq.x;
                acc[rr][1] += hv * wq.y;
                acc[rr][2] += hv * wq.z;
                acc[rr][3] += hv * wq.w;
            }
        }
        __syncthreads();
    }

    #pragma unroll
    for (int rr = 0; rr < 8; rr++) {
        const int r = row0 + ty * 8 + rr;
        float4 o;
        o.x = __uint_as_float(f2tf32(acc[rr][0]));
        o.y = __uint_as_float(f2tf32(acc[rr][1]));
        o.z = __uint_as_float(f2tf32(acc[rr][2]));
        o.w = __uint_as_float(f2tf32(acc[rr][3]));
        *(float4*)&g_Wh[(size_t)r * OUTD + tx * 4] = o;

        float s1 = acc[rr][0] * a1v[0] + acc[rr][1] * a1v[1] +
                   acc[rr][2] * a1v[2] + acc[rr][3] * a1v[3];
        float s2 = acc[rr][0] * a2v[0] + acc[rr][1] * a2v[1] +
                   acc[rr][2] * a2v[2] + acc[rr][3] * a2v[3];
        #pragma unroll
        for (int off = 16; off; off >>= 1) {
            s1 += __shfl_xor_sync(0xFFFFFFFFu, s1, off);
            s2 += __shfl_xor_sync(0xFFFFFFFFu, s2, off);
        }
        if (tx == 0) {
            g_E1[r] = expf(s1);
            g_G1[r] = expf(NEG_SLOPE * s1);
            g_E2[r] = expf(s2);
            g_G2[r] = expf(NEG_SLOPE * s2);
        }
    }
}

// ---------------------------------------------------------------------------
// Kernel 2: fused masked-softmax attention aggregate, tf32 mma.sync,
// cp.async double-buffered Wh/E2/G2 tiles, exp-free weight computation,
// m32n32 warp tiles (2 m-warps x 4 n-warps).
//
// per iter t (buf idx = t&1):
//   wait cp.async; sync#1          (buffers ready; MMA(t-1) done)
//   weights(t): w = max(Efi*Efj, Gfi*Gfj) * adj  -> wts (tf32), Z += w
//   sync#2
//   issue cp.async for tile t+1    (overlaps MMA)
//   MMA(t): acc += wts(64x64) @ WhS[idx](64x128)
// ---------------------------------------------------------------------------
#define WHS_STRIDE 136
#define WTS_STRIDE 68
#define SM_WHS  0                          // [2][64][136]
#define SM_WTS  (2 * 64 * WHS_STRIDE)      // [64][68]
#define SM_EJS  (SM_WTS + 64 * WTS_STRIDE) // [2][64]
#define SM_GJS  (SM_EJS + 128)             // [2][64]
#define SM_ZS   (SM_GJS + 128)             // [64]
#define SM_TOT  (SM_ZS + 64)
#define SM_BYTES (SM_TOT * 4)

__device__ __forceinline__ void mma_tf32(float* d, const uint32_t* a,
                                         uint32_t b0, uint32_t b1) {
    asm volatile(
        "mma.sync.aligned.m16n8k8.row.col.f32.tf32.tf32.f32 "
        "{%0,%1,%2,%3}, {%4,%5,%6,%7}, {%8,%9}, {%0,%1,%2,%3};\n"
        : "+f"(d[0]), "+f"(d[1]), "+f"(d[2]), "+f"(d[3])
        : "r"(a[0]), "r"(a[1]), "r"(a[2]), "r"(a[3]), "r"(b0), "r"(b1));
}

__global__ __launch_bounds__(256, 2) void k2_attn(
    const float* __restrict__ adj, float* __restrict__ out)
{
    extern __shared__ float sm[];
    float* WhS = sm + SM_WHS;    // [2][64][136] tf32 bits (from k1)
    float* wts = sm + SM_WTS;    // [64][68] tf32 bits
    float* ejs = sm + SM_EJS;    // [2][64] exp(f2)
    float* gjs = sm + SM_GJS;    // [2][64] exp(0.2 f2)
    float* Zs  = sm + SM_ZS;     // [64]
    const uint32_t* wtsu = (const uint32_t*)wts;

    const int t    = threadIdx.x;
    const int wid  = t >> 5;
    const int lane = t & 31;
    const int gid  = lane >> 2;
    const int tig  = lane & 3;
    const int b    = blockIdx.y;
    const int i0   = blockIdx.x * 64;

    // m32n32 warp tiles: 2 warps on M (32 rows each), 4 on N (32 cols each)
    const int m_warp = (wid & 1) * 32;
    const int n_warp = (wid >> 1) * 32;

    const int wr  = t >> 2;          // weight row 0..63
    const int wc0 = (t & 3) * 16;    // weight col base

    if (t < 64) Zs[t] = 0.f;

    const float Efi = g_E1[(size_t)b * NN + i0 + wr];
    const float Gfi = g_G1[(size_t)b * NN + i0 + wr];
    const float* Whb = g_Wh + (size_t)b * NN * OUTD;
    const float* E2b = g_E2 + (size_t)b * NN;
    const float* G2b = g_G2 + (size_t)b * NN;

    // ---- prologue: async-fill buffer 0 with tile 0
    {
        #pragma unroll
        for (int p = 0; p < 8; p++) {
            int c = t + p * 256;              // 0..2047
            int r = c >> 5, c16 = c & 31;
            cp_async16(&WhS[r * WHS_STRIDE + c16 * 4],
                       &Whb[(size_t)r * OUTD + c16 * 4]);
        }
        if (t < 16)      cp_async16(&ejs[t * 4],        &E2b[t * 4]);
        else if (t < 32) cp_async16(&gjs[(t - 16) * 4], &G2b[(t - 16) * 4]);
        CP_COMMIT();
    }

    float acc[2][4][4];
    #pragma unroll
    for (int u = 0; u < 2; u++)
        #pragma unroll
        for (int v = 0; v < 4; v++)
            #pragma unroll
            for (int j = 0; j < 4; j++) acc[u][v][j] = 0.f;

    float Zpart = 0.f;

    for (int tt = 0; tt < NN / 64; tt++) {
        const int idx = tt & 1;
        const int j0 = tt * 64;
        const uint32_t* WhBufu =
            (const uint32_t*)(WhS + idx * 64 * WHS_STRIDE);
        const float* ejBuf = ejs + idx * 64;
        const float* gjBuf = gjs + idx * 64;

        CP_WAIT0();
        __syncthreads();          // sync#1: buffers ready, MMA(t-1) done

        // ---- weight tile: 16 entries/thread, NO exp, branchless
        {
            const float* adjrow = adj + (size_t)(i0 + wr) * NN + j0 + wc0;
            #pragma unroll
            for (int q = 0; q < 4; q++) {
                float4 av = *(const float4*)&adjrow[q * 4];
                float4 ej = *(const float4*)&ejBuf[wc0 + q * 4];
                float4 gj = *(const float4*)&gjBuf[wc0 + q * 4];
                float am[4] = {av.x, av.y, av.z, av.w};
                float ev[4] = {ej.x, ej.y, ej.z, ej.w};
                float gv[4] = {gj.x, gj.y, gj.z, gj.w};
                uint32_t wb[4];
                #pragma unroll
                for (int s = 0; s < 4; s++) {
                    float w = fmaxf(Efi * ev[s], Gfi * gv[s]) * am[s];
                    uint32_t wt = f2tf32(w);
                    wb[s] = wt;
                    Zpart += __uint_as_float(wt);
                }
                *(uint4*)&wts[wr * WTS_STRIDE + wc0 + q * 4] =
                    make_uint4(wb[0], wb[1], wb[2], wb[3]);
            }
        }
        __syncthreads();          // sync#2: wts complete

        // ---- prefetch next tile (overlaps MMA below)
        if (tt + 1 < NN / 64) {
            const int j1 = j0 + 64;
            float* whdst = WhS + (idx ^ 1) * 64 * WHS_STRIDE;
            #pragma unroll
            for (int p = 0; p < 8; p++) {
                int c = t + p * 256;
                int r = c >> 5, c16 = c & 31;
                cp_async16(&whdst[r * WHS_STRIDE + c16 * 4],
                           &Whb[(size_t)(j1 + r) * OUTD + c16 * 4]);
            }
            if (t < 16)
                cp_async16(&ejs[(idx ^ 1) * 64 + t * 4], &E2b[j1 + t * 4]);
            else if (t < 32)
                cp_async16(&gjs[(idx ^ 1) * 64 + (t - 16) * 4],
                           &G2b[j1 + (t - 16) * 4]);
            CP_COMMIT();
        }

        // ---- tensor-core accumulate: acc += wts(64x64) @ WhBuf(64x128)
        #pragma unroll
        for (int k0 = 0; k0 < 64; k0 += 8) {
            uint32_t afrag[2][4];
            #pragma unroll
            for (int u = 0; u < 2; u++) {
                int base = (m_warp + u * 16 + gid) * WTS_STRIDE + k0 + tig;
                afrag[u][0] = wtsu[base];
                afrag[u][1] = wtsu[base + 8 * WTS_STRIDE];
                afrag[u][2] = wtsu[base + 4];
                afrag[u][3] = wtsu[base + 8 * WTS_STRIDE + 4];
            }
            #pragma unroll
            for (int v = 0; v < 4; v++) {
                int nb = n_warp + v * 8 + gid;
                uint32_t b0 = WhBufu[(k0 + tig) * WHS_STRIDE + nb];
                uint32_t b1 = WhBufu[(k0 + tig + 4) * WHS_STRIDE + nb];
                mma_tf32(acc[0][v], afrag[0], b0, b1);
                mma_tf32(acc[1][v], afrag[1], b0, b1);
            }
        }
    }

    atomicAdd(&Zs[wr], Zpart);
    __syncthreads();

    // ---- epilogue: divide by Z, store
    #pragma unroll
    for (int u = 0; u < 2; u++) {
        const int row0e = m_warp + u * 16 + gid;
        const int row1e = row0e + 8;
        const float inv0 = 1.f / Zs[row0e];
        const float inv1 = 1.f / Zs[row1e];
        float* out0 = out + ((size_t)b * NN + i0 + row0e) * OUTD;
        float* out1 = out + ((size_t)b * NN + i0 + row1e) * OUTD;
        #pragma unroll
        for (int v = 0; v < 4; v++) {
            int col = n_warp + v * 8 + tig * 2;
            *(float2*)&out0[col] = make_float2(acc[u][v][0] * inv0,
                                               acc[u][v][1] * inv0);
            *(float2*)&out1[col] = make_float2(acc[u][v][2] * inv1,
                                               acc[u][v][3] * inv1);
        }
    }
}

// ---------------------------------------------------------------------------
extern "C" void kernel_launch(void* const* d_in, const int* in_sizes, int n_in,
                              void* d_out, int out_size)
{
    const float* h   = (const float*)d_in[0];   // (8, 2048, 256)
    const float* adj = (const float*)d_in[1];   // (2048, 2048)
    const float* W   = (const float*)d_in[2];   // (256, 128)
    const float* a   = (const float*)d_in[3];   // (256,)
    float* out = (float*)d_out;                 // (8, 2048, 128)

    k1_gemm_wh<<<ROWS / 64, 256>>>(h, W, a);

    cudaFuncSetAttribute(k2_attn, cudaFuncAttributeMaxDynamicSharedMemorySize,
                         SM_BYTES);
    k2_attn<<<dim3(NN / 64, BB), 256, SM_BYTES>>>(adj, out);
}

// round 9
// speedup vs baseline: 1.2573x; 1.2471x over previous
#include <cuda_runtime.h>
#include <cuda_fp16.h>
#include <cstdint>

#define BB 8
#define NN 2048
#define IND 256
#define OUTD 128
#define ROWS (BB * NN)   // 16384
#define NEG_SLOPE 0.2f

// Scratch (device globals — no allocation allowed)
__device__ __half g_WhT[(size_t)ROWS * OUTD];  // 4 MB, per-batch [o][j] fp16
__device__ float g_E1[ROWS];          // exp(f1)
__device__ float g_G1[ROWS];          // exp(0.2*f1)
__device__ float g_E2[ROWS];          // exp(f2)
__device__ float g_G2[ROWS];          // exp(0.2*f2)

__device__ __forceinline__ void cp_async16(void* dst_smem, const void* src) {
    uint32_t d = (uint32_t)__cvta_generic_to_shared(dst_smem);
    asm volatile("cp.async.cg.shared.global [%0], [%1], 16;\n"
                 :: "r"(d), "l"(src));
}
#define CP_COMMIT() asm volatile("cp.async.commit_group;\n" ::: "memory")
#define CP_WAIT0()  asm volatile("cp.async.wait_group 0;\n" ::: "memory")

// ---------------------------------------------------------------------------
// Kernel 1: Wh = h @ W  (16384x256 @ 256x128).
// Epilogue: f1 = Wh·a1, f2 = Wh·a2 (full precision), store exp factors so k2
// needs NO exp:  exp(leaky(fi+fj)) == max(E1[i]*E2[j], G1[i]*G2[j]).
// Wh is stored fp16 TRANSPOSED per batch: g_WhT[b][o][j]  (o-major rows),
// so k2's B operand (col-major k x n for mma) cp.asyncs directly.
// Each thread owns 8 consecutive j-rows of 4 columns -> per column the 8
// fp16 values pack into ONE uint4 store at WhT[c][j0..j0+7].
// ---------------------------------------------------------------------------
__global__ __launch_bounds__(256) void k1_gemm_wh(
    const float* __restrict__ h, const float* __restrict__ W,
    const float* __restrict__ a)
{
    __shared__ float hs[64][32];
    __shared__ float Ws[32][128];

    const int t  = threadIdx.x;
    const int ty = t >> 5;
    const int tx = t & 31;
    const int row0 = blockIdx.x * 64;

    float acc[8][4];
    #pragma unroll
    for (int i = 0; i < 8; i++)
        #pragma unroll
        for (int j = 0; j < 4; j++) acc[i][j] = 0.f;

    float a1v[4], a2v[4];
    #pragma unroll
    for (int cc = 0; cc < 4; cc++) {
        a1v[cc] = a[tx * 4 + cc];
        a2v[cc] = a[OUTD + tx * 4 + cc];
    }

    const int lr = t >> 3;
    const int lc = (t & 7) * 4;

    for (int k0 = 0; k0 < IND; k0 += 32) {
        *(float4*)&hs[lr][lc] =
            *(const float4*)&h[(size_t)(row0 + lr) * IND + k0 + lc];
        *(float4*)&hs[lr + 32][lc] =
            *(const float4*)&h[(size_t)(row0 + lr + 32) * IND + k0 + lc];
        #pragma unroll
        for (int p = 0; p < 4; p++) {
            int idx = t * 4 + p * 1024;
            int wr = idx >> 7, wc = idx & 127;
            *(float4*)&Ws[wr][wc] = *(const float4*)&W[(size_t)(k0 + wr) * OUTD + wc];
        }
        __syncthreads();

        #pragma unroll 8
        for (int kk = 0; kk < 32; kk++) {
            float4 wq = *(const float4*)&Ws[kk][tx * 4];
            #pragma unroll
            for (int rr = 0; rr < 8; rr++) {
                float hv = hs[ty * 8 + rr][kk];
                acc[rr][0] += hv * wq.x;
                acc[rr][1] += hv * wq.y;
                acc[rr][2] += hv * wq.z;
                acc[rr][3] += hv * wq.w;
            }
        }
        __syncthreads();
    }

    // ---- store Wh transposed fp16: for each of my 4 cols, pack 8 j-rows
    {
        const int bb = row0 >> 11;             // batch
        const int jloc = (row0 & (NN - 1)) + ty * 8;
        __half* WhTb = g_WhT + (size_t)bb * OUTD * NN;
        #pragma unroll
        for (int cc = 0; cc < 4; cc++) {
            const int c = tx * 4 + cc;
            __half hv[8];
            #pragma unroll
            for (int rr = 0; rr < 8; rr++) hv[rr] = __float2half_rn(acc[rr][cc]);
            *(uint4*)&WhTb[(size_t)c * NN + jloc] = *(const uint4*)hv;
        }
    }

    #pragma unroll
    for (int rr = 0; rr < 8; rr++) {
        const int r = row0 + ty * 8 + rr;
        float s1 = acc[rr][0] * a1v[0] + acc[rr][1] * a1v[1] +
                   acc[rr][2] * a1v[2] + acc[rr][3] * a1v[3];
        float s2 = acc[rr][0] * a2v[0] + acc[rr][1] * a2v[1] +
                   acc[rr][2] * a2v[2] + acc[rr][3] * a2v[3];
        #pragma unroll
        for (int off = 16; off; off >>= 1) {
            s1 += __shfl_xor_sync(0xFFFFFFFFu, s1, off);
            s2 += __shfl_xor_sync(0xFFFFFFFFu, s2, off);
        }
        if (tx == 0) {
            g_E1[r] = expf(s1);
            g_G1[r] = expf(NEG_SLOPE * s1);
            g_E2[r] = expf(s2);
            g_G2[r] = expf(NEG_SLOPE * s2);
        }
    }
}

// ---------------------------------------------------------------------------
// Kernel 2: fused masked-softmax attention aggregate, fp16 mma m16n8k16,
// exp-free weights, cp.async double-buffered WhT tiles, m32n32 warp tiles.
//
// smem (32-bit words):
//   WhT[2][128][36]  n-major fp16 tile, stride 36 words (72 halves)
//   wts[64][36]      fp16 weight tile, stride 36 words
//   ejs/gjs[2][64], Zs[64]
// Fragment loads (stride 36): addr%32 = 4*gid + tig  -> conflict-free.
// ---------------------------------------------------------------------------
#define BSTRIDE 36
#define WHT_WORDS (128 * BSTRIDE)          // per buffer
#define SM_WHT 0                            // [2][WHT_WORDS]
#define SM_WTS (2 * WHT_WORDS)              // [64][36]
#define SM_EJS (SM_WTS + 64 * BSTRIDE)      // [2][64]
#define SM_GJS (SM_EJS + 128)               // [2][64]
#define SM_ZS  (SM_GJS + 128)               // [64]
#define SM_TOT (SM_ZS + 64)
#define SM_BYTES (SM_TOT * 4)

__device__ __forceinline__ void mma_f16(float* d, const uint32_t* a,
                                        uint32_t b0, uint32_t b1) {
    asm volatile(
        "mma.sync.aligned.m16n8k16.row.col.f32.f16.f16.f32 "
        "{%0,%1,%2,%3}, {%4,%5,%6,%7}, {%8,%9}, {%0,%1,%2,%3};\n"
        : "+f"(d[0]), "+f"(d[1]), "+f"(d[2]), "+f"(d[3])
        : "r"(a[0]), "r"(a[1]), "r"(a[2]), "r"(a[3]), "r"(b0), "r"(b1));
}

__global__ __launch_bounds__(256, 2) void k2_attn(
    const float* __restrict__ adj, float* __restrict__ out)
{
    extern __shared__ uint32_t smw[];
    uint32_t* WhTs = smw + SM_WHT;     // [2][128][36]
    uint32_t* wts  = smw + SM_WTS;     // [64][36]
    float* ejs = (float*)(smw + SM_EJS);
    float* gjs = (float*)(smw + SM_GJS);
    float* Zs  = (float*)(smw + SM_ZS);

    const int t    = threadIdx.x;
    const int wid  = t >> 5;
    const int lane = t & 31;
    const int gid  = lane >> 2;
    const int tig  = lane & 3;
    const int b    = blockIdx.y;
    const int i0   = blockIdx.x * 64;

    // m32n32 warp tiles: 2 warps on M, 4 on N
    const int m_warp = (wid & 1) * 32;
    const int n_warp = (wid >> 1) * 32;

    const int wr  = t >> 2;          // weight row 0..63
    const int wc0 = (t & 3) * 16;    // weight col base

    if (t < 64) Zs[t] = 0.f;

    const float Efi = g_E1[(size_t)b * NN + i0 + wr];
    const float Gfi = g_G1[(size_t)b * NN + i0 + wr];
    const __half* WhTb = g_WhT + (size_t)b * OUTD * NN;
    const float* E2b = g_E2 + (size_t)b * NN;
    const float* G2b = g_G2 + (size_t)b * NN;

    // ---- prologue: async-fill buffer 0 with tile 0
    // WhT tile: 128 o-rows x 64 fp16 (=128B) -> 1024 16B chunks, 4/thread
    {
        #pragma unroll
        for (int p = 0; p < 4; p++) {
            int c = t + p * 256;            // chunk 0..1023
            int o = c >> 3, ch = c & 7;
            cp_async16(&WhTs[o * BSTRIDE + ch * 4],
                       &WhTb[(size_t)o * NN + ch * 8]);
        }
        if (t < 16)      cp_async16(&ejs[t * 4],        &E2b[t * 4]);
        else if (t < 32) cp_async16(&gjs[(t - 16) * 4], &G2b[(t - 16) * 4]);
        CP_COMMIT();
    }

    float acc[2][4][4];
    #pragma unroll
    for (int u = 0; u < 2; u++)
        #pragma unroll
        for (int v = 0; v < 4; v++)
            #pragma unroll
            for (int j = 0; j < 4; j++) acc[u][v][j] = 0.f;

    float Zpart = 0.f;

    for (int tt = 0; tt < NN / 64; tt++) {
        const int idx = tt & 1;
        const int j0 = tt * 64;
        const uint32_t* WhBuf = WhTs + idx * WHT_WORDS;
        const float* ejBuf = ejs + idx * 64;
        const float* gjBuf = gjs + idx * 64;

        CP_WAIT0();
        __syncthreads();          // sync#1: buffers ready, MMA(t-1) done

        // ---- weight tile: 16 entries/thread, no exp, fp16-rounded
        {
            const float* adjrow = adj + (size_t)(i0 + wr) * NN + j0 + wc0;
            uint32_t wb[8];
            #pragma unroll
            for (int q = 0; q < 4; q++) {
                float4 av = *(const float4*)&adjrow[q * 4];
                float4 ej = *(const float4*)&ejBuf[wc0 + q * 4];
                float4 gj = *(const float4*)&gjBuf[wc0 + q * 4];
                float w0 = fmaxf(Efi * ej.x, Gfi * gj.x) * av.x;
                float w1 = fmaxf(Efi * ej.y, Gfi * gj.y) * av.y;
                float w2 = fmaxf(Efi * ej.z, Gfi * gj.z) * av.z;
                float w3 = fmaxf(Efi * ej.w, Gfi * gj.w) * av.w;
                __half2 p0 = __floats2half2_rn(w0, w1);
                __half2 p1 = __floats2half2_rn(w2, w3);
                float2 r0 = __half22float2(p0);
                float2 r1 = __half22float2(p1);
                Zpart += (r0.x + r0.y) + (r1.x + r1.y);
                wb[q * 2]     = *(const uint32_t*)&p0;
                wb[q * 2 + 1] = *(const uint32_t*)&p1;
            }
            uint32_t* dst = &wts[wr * BSTRIDE + (t & 3) * 8];
            *(uint4*)dst       = make_uint4(wb[0], wb[1], wb[2], wb[3]);
            *(uint4*)(dst + 4) = make_uint4(wb[4], wb[5], wb[6], wb[7]);
        }
        __syncthreads();          // sync#2: wts complete

        // ---- prefetch next tile (overlaps MMA below)
        if (tt + 1 < NN / 64) {
            const int j1 = j0 + 64;
            uint32_t* whdst = WhTs + (idx ^ 1) * WHT_WORDS;
            #pragma unroll
            for (int p = 0; p < 4; p++) {
                int c = t + p * 256;
                int o = c >> 3, ch = c & 7;
                cp_async16(&whdst[o * BSTRIDE + ch * 4],
                           &WhTb[(size_t)o * NN + j1 + ch * 8]);
            }
            if (t < 16)
                cp_async16(&ejs[(idx ^ 1) * 64 + t * 4], &E2b[j1 + t * 4]);
            else if (t < 32)
                cp_async16(&gjs[(idx ^ 1) * 64 + (t - 16) * 4],
                           &G2b[j1 + (t - 16) * 4]);
            CP_COMMIT();
        }

        // ---- fp16 tensor-core accumulate: acc += wts(64x64) @ Wh(64x128)
        #pragma unroll
        for (int kw = 0; kw < 4; kw++) {         // k16 steps over 64
            const int kcol = kw * 8 + tig;       // word col in [0,32)
            uint32_t afrag[2][4];
            #pragma unroll
            for (int u = 0; u < 2; u++) {
                int rb = (m_warp + u * 16 + gid) * BSTRIDE;
                afrag[u][0] = wts[rb + kcol];
                afrag[u][1] = wts[rb + 8 * BSTRIDE + kcol];
                afrag[u][2] = wts[rb + kcol + 4];
                afrag[u][3] = wts[rb + 8 * BSTRIDE + kcol + 4];
            }
            #pragma unroll
            for (int v = 0; v < 4; v++) {
                int nb = (n_warp + v * 8 + gid) * BSTRIDE;
                uint32_t b0 = WhBuf[nb + kcol];
                uint32_t b1 = WhBuf[nb + kcol + 4];
                mma_f16(acc[0][v], afrag[0], b0, b1);
                mma_f16(acc[1][v], afrag[1], b0, b1);
            }
        }
    }

    atomicAdd(&Zs[wr], Zpart);
    __syncthreads();

    // ---- epilogue: divide by Z, store
    #pragma unroll
    for (int u = 0; u < 2; u++) {
        const int row0e = m_warp + u * 16 + gid;
        const int row1e = row0e + 8;
        const float inv0 = 1.f / Zs[row0e];
        const float inv1 = 1.f / Zs[row1e];
        float* out0 = out + ((size_t)b * NN + i0 + row0e) * OUTD;
        float* out1 = out + ((size_t)b * NN + i0 + row1e) * OUTD;
        #pragma unroll
        for (int v = 0; v < 4; v++) {
            int col = n_warp + v * 8 + tig * 2;
            *(float2*)&out0[col] = make_float2(acc[u][v][0] * inv0,
                                               acc[u][v][1] * inv0);
            *(float2*)&out1[col] = make_float2(acc[u][v][2] * inv1,
                                               acc[u][v][3] * inv1);
        }
    }
}

// ---------------------------------------------------------------------------
extern "C" void kernel_launch(void* const* d_in, const int* in_sizes, int n_in,
                              void* d_out, int out_size)
{
    const float* h   = (const float*)d_in[0];   // (8, 2048, 256)
    const float* adj = (const float*)d_in[1];   // (2048, 2048)
    const float* W   = (const float*)d_in[2];   // (256, 128)
    const float* a   = (const float*)d_in[3];   // (256,)
    float* out = (float*)d_out;                 // (8, 2048, 128)

    k1_gemm_wh<<<ROWS / 64, 256>>>(h, W, a);

    cudaFuncSetAttribute(k2_attn, cudaFuncAttributeMaxDynamicSharedMemorySize,
                         SM_BYTES);
    k2_attn<<<dim3(NN / 64, BB), 256, SM_BYTES>>>(adj, out);
}

// round 11
// speedup vs baseline: 1.3816x; 1.0988x over previous
#include <cuda_runtime.h>
#include <cuda_fp16.h>
#include <cstdint>

#define BB 8
#define NN 2048
#define IND 256
#define OUTD 128
#define ROWS (BB * NN)   // 16384
#define NEG_SLOPE 0.2f

// Scratch (device globals — no allocation allowed)
__device__ __half g_WhT[(size_t)ROWS * OUTD];  // 4 MB, per-batch [o][j] fp16
__device__ float g_E1[ROWS];          // exp(f1)
__device__ float g_G1[ROWS];          // exp(0.2*f1)
__device__ float g_E2[ROWS];          // exp(f2)
__device__ float g_G2[ROWS];          // exp(0.2*f2)

__device__ __forceinline__ void cp_async16(void* dst_smem, const void* src) {
    uint32_t d = (uint32_t)__cvta_generic_to_shared(dst_smem);
    asm volatile("cp.async.cg.shared.global [%0], [%1], 16;\n"
                 :: "r"(d), "l"(src));
}
#define CP_COMMIT() asm volatile("cp.async.commit_group;\n" ::: "memory")
#define CP_WAIT(N)  asm volatile("cp.async.wait_group %0;\n" :: "n"(N) : "memory")

// ---------------------------------------------------------------------------
// Kernel 1: Wh = h @ W (unchanged, proven). f1/f2 full precision -> exp
// factors; Wh stored fp16 transposed per batch: g_WhT[b][o][j].
// ---------------------------------------------------------------------------
__global__ __launch_bounds__(256) void k1_gemm_wh(
    const float* __restrict__ h, const float* __restrict__ W,
    const float* __restrict__ a)
{
    __shared__ float hs[64][32];
    __shared__ float Ws[32][128];

    const int t  = threadIdx.x;
    const int ty = t >> 5;
    const int tx = t & 31;
    const int row0 = blockIdx.x * 64;

    float acc[8][4];
    #pragma unroll
    for (int i = 0; i < 8; i++)
        #pragma unroll
        for (int j = 0; j < 4; j++) acc[i][j] = 0.f;

    float a1v[4], a2v[4];
    #pragma unroll
    for (int cc = 0; cc < 4; cc++) {
        a1v[cc] = a[tx * 4 + cc];
        a2v[cc] = a[OUTD + tx * 4 + cc];
    }

    const int lr = t >> 3;
    const int lc = (t & 7) * 4;

    for (int k0 = 0; k0 < IND; k0 += 32) {
        *(float4*)&hs[lr][lc] =
            *(const float4*)&h[(size_t)(row0 + lr) * IND + k0 + lc];
        *(float4*)&hs[lr + 32][lc] =
            *(const float4*)&h[(size_t)(row0 + lr + 32) * IND + k0 + lc];
        #pragma unroll
        for (int p = 0; p < 4; p++) {
            int idx = t * 4 + p * 1024;
            int wr = idx >> 7, wc = idx & 127;
            *(float4*)&Ws[wr][wc] = *(const float4*)&W[(size_t)(k0 + wr) * OUTD + wc];
        }
        __syncthreads();

        #pragma unroll 8
        for (int kk = 0; kk < 32; kk++) {
            float4 wq = *(const float4*)&Ws[kk][tx * 4];
            #pragma unroll
            for (int rr = 0; rr < 8; rr++) {
                float hv = hs[ty * 8 + rr][kk];
                acc[rr][0] += hv * wq.x;
                acc[rr][1] += hv * wq.y;
                acc[rr][2] += hv * wq.z;
                acc[rr][3] += hv * wq.w;
            }
        }
        __syncthreads();
    }

    {
        const int bb = row0 >> 11;             // batch
        const int jloc = (row0 & (NN - 1)) + ty * 8;
        __half* WhTb = g_WhT + (size_t)bb * OUTD * NN;
        #pragma unroll
        for (int cc = 0; cc < 4; cc++) {
            const int c = tx * 4 + cc;
            __half hv[8];
            #pragma unroll
            for (int rr = 0; rr < 8; rr++) hv[rr] = __float2half_rn(acc[rr][cc]);
            *(uint4*)&WhTb[(size_t)c * NN + jloc] = *(const uint4*)hv;
        }
    }

    #pragma unroll
    for (int rr = 0; rr < 8; rr++) {
        const int r = row0 + ty * 8 + rr;
        float s1 = acc[rr][0] * a1v[0] + acc[rr][1] * a1v[1] +
                   acc[rr][2] * a1v[2] + acc[rr][3] * a1v[3];
        float s2 = acc[rr][0] * a2v[0] + acc[rr][1] * a2v[1] +
                   acc[rr][2] * a2v[2] + acc[rr][3] * a2v[3];
        #pragma unroll
        for (int off = 16; off; off >>= 1) {
            s1 += __shfl_xor_sync(0xFFFFFFFFu, s1, off);
            s2 += __shfl_xor_sync(0xFFFFFFFFu, s2, off);
        }
        if (tx == 0) {
            g_E1[r] = expf(s1);
            g_G1[r] = expf(NEG_SLOPE * s1);
            g_E2[r] = expf(s2);
            g_G2[r] = expf(NEG_SLOPE * s2);
        }
    }
}

// ---------------------------------------------------------------------------
// Kernel 2: fp16 mma m16n8k16, ldmatrix fragments, ONE barrier per tile.
// adj/E2/G2 read by direct LDG in the weight phase (L2-resident; this is the
// round-9-proven placement — no cross-thread smem visibility needed).
// Wh tile cp.async double-buffered; wts double-buffered (WAR distance 2 tiles
// with a barrier between -> single __syncthreads per tile is sufficient:
//   weights(t)->wts[p] happens after sync(t-1); last reads of wts[p] were
//   MMA(t-2), issued before sync(t-1) in every warp's program order).
// per tile t (p = t&1):
//   weights(t): LDG adj/ej/gj, compute, STS -> wts[p]
//   CP_WAIT(0)        (own Wh(t) chunks landed)
//   __syncthreads()   (all Wh(t)+wts(t) visible; MMA(t-1) done everywhere)
//   prefetch Wh(t+1)  (overlaps MMA(t) and weights(t+1))
//   MMA(t): ldmatrix.x4 A/B + 32 mma
// ---------------------------------------------------------------------------
#define BSTRIDE 36                    // words per fragment row (72 halves)
#define WHT_WORDS (128 * BSTRIDE)     // 4608 per buffer
#define WTS_WORDS (64 * BSTRIDE)      // 2304 per buffer
#define SM_WHT 0                       // [2][WHT_WORDS]
#define SM_WTS (2 * WHT_WORDS)         // 9216, [2][WTS_WORDS]
#define SM_ZS  (SM_WTS + 2 * WTS_WORDS)  // 13824
#define SM_TOT (SM_ZS + 64)
#define SM_BYTES (SM_TOT * 4)          // 55552 B

__device__ __forceinline__ void mma_f16(float* d, const uint32_t* a,
                                        uint32_t b0, uint32_t b1) {
    asm volatile(
        "mma.sync.aligned.m16n8k16.row.col.f32.f16.f16.f32 "
        "{%0,%1,%2,%3}, {%4,%5,%6,%7}, {%8,%9}, {%0,%1,%2,%3};\n"
        : "+f"(d[0]), "+f"(d[1]), "+f"(d[2]), "+f"(d[3])
        : "r"(a[0]), "r"(a[1]), "r"(a[2]), "r"(a[3]), "r"(b0), "r"(b1));
}

__device__ __forceinline__ void ldsm4(uint32_t addr, uint32_t* r) {
    asm volatile("ldmatrix.sync.aligned.m8n8.x4.shared.b16 {%0,%1,%2,%3}, [%4];"
                 : "=r"(r[0]), "=r"(r[1]), "=r"(r[2]), "=r"(r[3]) : "r"(addr));
}

__device__ __forceinline__ void prefetch_wh(uint32_t* WhTs,
                                            const __half* WhTb,
                                            int buf, int j0, int t) {
    uint32_t* whDst = WhTs + buf * WHT_WORDS;
    #pragma unroll
    for (int p = 0; p < 4; p++) {
        int c = t + p * 256;            // chunk 0..1023
        int o = c >> 3, ch = c & 7;
        cp_async16(&whDst[o * BSTRIDE + ch * 4],
                   &WhTb[(size_t)o * NN + j0 + ch * 8]);
    }
    CP_COMMIT();
}

__global__ __launch_bounds__(256, 2) void k2_attn(
    const float* __restrict__ adj, float* __restrict__ out)
{
    extern __shared__ uint32_t smw[];
    uint32_t* WhTs = smw + SM_WHT;
    uint32_t* wts  = smw + SM_WTS;
    float* Zs = (float*)(smw + SM_ZS);

    const int t    = threadIdx.x;
    const int wid  = t >> 5;
    const int lane = t & 31;
    const int gid  = lane >> 2;
    const int tig  = lane & 3;
    const int b    = blockIdx.y;
    const int i0   = blockIdx.x * 64;

    const int m_warp = (wid & 1) * 32;      // 2 m-warps x 4 n-warps
    const int n_warp = (wid >> 1) * 32;

    const int wr  = t >> 2;          // weight row 0..63
    const int wc0 = (t & 3) * 16;    // weight col base

    if (t < 64) Zs[t] = 0.f;

    const float Efi = g_E1[(size_t)b * NN + i0 + wr];
    const float Gfi = g_G1[(size_t)b * NN + i0 + wr];
    const __half* WhTb = g_WhT + (size_t)b * OUTD * NN;
    const float* E2b = g_E2 + (size_t)b * NN;
    const float* G2b = g_G2 + (size_t)b * NN;
    const float* adjrow = adj + (size_t)(i0 + wr) * NN + wc0;

    // ldmatrix lane base addresses (shared-space byte offsets)
    const uint32_t smem0 = (uint32_t)__cvta_generic_to_shared(smw);
    const uint32_t aBase = smem0 + SM_WTS * 4 +
        (uint32_t)(((m_warp + (lane & 15)) * BSTRIDE + (lane >> 4) * 4) * 4);
    const uint32_t bBase = smem0 + SM_WHT * 4 +
        (uint32_t)(((n_warp + ((lane >> 4) & 1) * 8 + (lane & 7)) * BSTRIDE +
                    ((lane >> 3) & 1) * 4) * 4);

    // prologue: Wh tile 0
    prefetch_wh(WhTs, WhTb, 0, 0, t);

    float acc[2][4][4];
    #pragma unroll
    for (int u = 0; u < 2; u++)
        #pragma unroll
        for (int v = 0; v < 4; v++)
            #pragma unroll
            for (int j = 0; j < 4; j++) acc[u][v][j] = 0.f;

    float Zpart = 0.f;

    for (int tt = 0; tt < NN / 64; tt++) {
        const int idx = tt & 1;
        const int j0 = tt * 64;

        // ---- weight tile: direct LDG (L2-resident), fp16-rounded
        {
            uint32_t wb[8];
            #pragma unroll
            for (int q = 0; q < 4; q++) {
                float4 av = *(const float4*)&adjrow[j0 + q * 4];
                float4 ej = *(const float4*)&E2b[j0 + wc0 + q * 4];
                float4 gj = *(const float4*)&G2b[j0 + wc0 + q * 4];
                float w0 = fmaxf(Efi * ej.x, Gfi * gj.x) * av.x;
                float w1 = fmaxf(Efi * ej.y, Gfi * gj.y) * av.y;
                float w2 = fmaxf(Efi * ej.z, Gfi * gj.z) * av.z;
                float w3 = fmaxf(Efi * ej.w, Gfi * gj.w) * av.w;
                __half2 p0 = __floats2half2_rn(w0, w1);
                __half2 p1 = __floats2half2_rn(w2, w3);
                float2 r0 = __half22float2(p0);
                float2 r1 = __half22float2(p1);
                Zpart += (r0.x + r0.y) + (r1.x + r1.y);
                wb[q * 2]     = *(const uint32_t*)&p0;
                wb[q * 2 + 1] = *(const uint32_t*)&p1;
            }
            uint32_t* dst = &wts[idx * WTS_WORDS + wr * BSTRIDE + (t & 3) * 8];
            *(uint4*)dst       = make_uint4(wb[0], wb[1], wb[2], wb[3]);
            *(uint4*)(dst + 4) = make_uint4(wb[4], wb[5], wb[6], wb[7]);
        }

        CP_WAIT(0);               // own Wh(tt) chunks landed
        __syncthreads();          // the ONE barrier per tile

        if (tt + 1 < NN / 64)
            prefetch_wh(WhTs, WhTb, idx ^ 1, j0 + 64, t);

        // ---- MMA via ldmatrix: acc += wts(64x64) @ Wh(64x128)
        const uint32_t aT = aBase + (uint32_t)(idx * WTS_WORDS * 4);
        const uint32_t bT = bBase + (uint32_t)(idx * WHT_WORDS * 4);
        #pragma unroll
        for (int kw = 0; kw < 4; kw++) {
            uint32_t af[2][4], bf[2][4];
            ldsm4(aT + kw * 32,        af[0]);
            ldsm4(aT + 2304 + kw * 32, af[1]);   // +16 rows * 144 B
            ldsm4(bT + kw * 32,        bf[0]);   // n 0..15
            ldsm4(bT + 2304 + kw * 32, bf[1]);   // n 16..31
            #pragma unroll
            for (int u = 0; u < 2; u++) {
                mma_f16(acc[u][0], af[u], bf[0][0], bf[0][1]);
                mma_f16(acc[u][1], af[u], bf[0][2], bf[0][3]);
                mma_f16(acc[u][2], af[u], bf[1][0], bf[1][1]);
                mma_f16(acc[u][3], af[u], bf[1][2], bf[1][3]);
            }
        }
    }

    atomicAdd(&Zs[wr], Zpart);
    __syncthreads();

    // ---- epilogue: divide by Z, store
    #pragma unroll
    for (int u = 0; u < 2; u++) {
        const int row0e = m_warp + u * 16 + gid;
        const int row1e = row0e + 8;
        const float inv0 = 1.f / Zs[row0e];
        const float inv1 = 1.f / Zs[row1e];
        float* out0 = out + ((size_t)b * NN + i0 + row0e) * OUTD;
        float* out1 = out + ((size_t)b * NN + i0 + row1e) * OUTD;
        #pragma unroll
        for (int v = 0; v < 4; v++) {
            int col = n_warp + v * 8 + tig * 2;
            *(float2*)&out0[col] = make_float2(acc[u][v][0] * inv0,
                                               acc[u][v][1] * inv0);
            *(float2*)&out1[col] = make_float2(acc[u][v][2] * inv1,
                                               acc[u][v][3] * inv1);
        }
    }
}

// ---------------------------------------------------------------------------
extern "C" void kernel_launch(void* const* d_in, const int* in_sizes, int n_in,
                              void* d_out, int out_size)
{
    const float* h   = (const float*)d_in[0];   // (8, 2048, 256)
    const float* adj = (const float*)d_in[1];   // (2048, 2048)
    const float* W   = (const float*)d_in[2];   // (256, 128)
    const float* a   = (const float*)d_in[3];   // (256,)
    float* out = (float*)d_out;                 // (8, 2048, 128)

    k1_gemm_wh<<<ROWS / 64, 256>>>(h, W, a);

    cudaFuncSetAttribute(k2_attn, cudaFuncAttributeMaxDynamicSharedMemorySize,
                         SM_BYTES);
    k2_attn<<<dim3(NN / 64, BB), 256, SM_BYTES>>>(adj, out);
}

// round 12
// speedup vs baseline: 1.3922x; 1.0077x over previous
#include <cuda_runtime.h>
#include <cuda_fp16.h>
#include <cstdint>

#define BB 8
#define NN 2048
#define IND 256
#define OUTD 128
#define ROWS (BB * NN)   // 16384
#define NEG_SLOPE 0.2f

// Scratch (device globals — no allocation allowed)
__device__ __half g_WhT[(size_t)ROWS * OUTD];  // 4 MB, per-batch [o][j] fp16
__device__ float g_E1[ROWS];          // exp(f1)
__device__ float g_G1[ROWS];          // exp(0.2*f1)
__device__ float g_E2[ROWS];          // exp(f2)
__device__ float g_G2[ROWS];          // exp(0.2*f2)

__device__ __forceinline__ void cp_async16(void* dst_smem, const void* src) {
    uint32_t d = (uint32_t)__cvta_generic_to_shared(dst_smem);
    asm volatile("cp.async.cg.shared.global [%0], [%1], 16;\n"
                 :: "r"(d), "l"(src));
}
#define CP_COMMIT() asm volatile("cp.async.commit_group;\n" ::: "memory")
#define CP_WAIT(N)  asm volatile("cp.async.wait_group %0;\n" :: "n"(N) : "memory")

// ---------------------------------------------------------------------------
// Kernel 1: Wh = h @ W (unchanged, proven). f1/f2 full precision -> exp
// factors; Wh stored fp16 transposed per batch: g_WhT[b][o][j].
// ---------------------------------------------------------------------------
__global__ __launch_bounds__(256) void k1_gemm_wh(
    const float* __restrict__ h, const float* __restrict__ W,
    const float* __restrict__ a)
{
    __shared__ float hs[64][32];
    __shared__ float Ws[32][128];

    const int t  = threadIdx.x;
    const int ty = t >> 5;
    const int tx = t & 31;
    const int row0 = blockIdx.x * 64;

    float acc[8][4];
    #pragma unroll
    for (int i = 0; i < 8; i++)
        #pragma unroll
        for (int j = 0; j < 4; j++) acc[i][j] = 0.f;

    float a1v[4], a2v[4];
    #pragma unroll
    for (int cc = 0; cc < 4; cc++) {
        a1v[cc] = a[tx * 4 + cc];
        a2v[cc] = a[OUTD + tx * 4 + cc];
    }

    const int lr = t >> 3;
    const int lc = (t & 7) * 4;

    for (int k0 = 0; k0 < IND; k0 += 32) {
        *(float4*)&hs[lr][lc] =
            *(const float4*)&h[(size_t)(row0 + lr) * IND + k0 + lc];
        *(float4*)&hs[lr + 32][lc] =
            *(const float4*)&h[(size_t)(row0 + lr + 32) * IND + k0 + lc];
        #pragma unroll
        for (int p = 0; p < 4; p++) {
            int idx = t * 4 + p * 1024;
            int wr = idx >> 7, wc = idx & 127;
            *(float4*)&Ws[wr][wc] = *(const float4*)&W[(size_t)(k0 + wr) * OUTD + wc];
        }
        __syncthreads();

        #pragma unroll 8
        for (int kk = 0; kk < 32; kk++) {
            float4 wq = *(const float4*)&Ws[kk][tx * 4];
            #pragma unroll
            for (int rr = 0; rr < 8; rr++) {
                float hv = hs[ty * 8 + rr][kk];
                acc[rr][0] += hv * wq.x;
                acc[rr][1] += hv * wq.y;
                acc[rr][2] += hv * wq.z;
                acc[rr][3] += hv * wq.w;
            }
        }
        __syncthreads();
    }

    {
        const int bb = row0 >> 11;             // batch
        const int jloc = (row0 & (NN - 1)) + ty * 8;
        __half* WhTb = g_WhT + (size_t)bb * OUTD * NN;
        #pragma unroll
        for (int cc = 0; cc < 4; cc++) {
            const int c = tx * 4 + cc;
            __half hv[8];
            #pragma unroll
            for (int rr = 0; rr < 8; rr++) hv[rr] = __float2half_rn(acc[rr][cc]);
            *(uint4*)&WhTb[(size_t)c * NN + jloc] = *(const uint4*)hv;
        }
    }

    #pragma unroll
    for (int rr = 0; rr < 8; rr++) {
        const int r = row0 + ty * 8 + rr;
        float s1 = acc[rr][0] * a1v[0] + acc[rr][1] * a1v[1] +
                   acc[rr][2] * a1v[2] + acc[rr][3] * a1v[3];
        float s2 = acc[rr][0] * a2v[0] + acc[rr][1] * a2v[1] +
                   acc[rr][2] * a2v[2] + acc[rr][3] * a2v[3];
        #pragma unroll
        for (int off = 16; off; off >>= 1) {
            s1 += __shfl_xor_sync(0xFFFFFFFFu, s1, off);
            s2 += __shfl_xor_sync(0xFFFFFFFFu, s2, off);
        }
        if (tx == 0) {
            g_E1[r] = expf(s1);
            g_G1[r] = expf(NEG_SLOPE * s1);
            g_E2[r] = expf(s2);
            g_G2[r] = expf(NEG_SLOPE * s2);
        }
    }
}

// ---------------------------------------------------------------------------
// Kernel 2: fp16 mma m16n8k16, ldmatrix fragments, ONE barrier per tile.
// adj/E2/G2 read by direct LDG in the weight phase (L2-resident; this is the
// round-9-proven placement — no cross-thread smem visibility needed).
// Wh tile cp.async double-buffered; wts double-buffered (WAR distance 2 tiles
// with a barrier between -> single __syncthreads per tile is sufficient:
//   weights(t)->wts[p] happens after sync(t-1); last reads of wts[p] were
//   MMA(t-2), issued before sync(t-1) in every warp's program order).
// per tile t (p = t&1):
//   weights(t): LDG adj/ej/gj, compute, STS -> wts[p]
//   CP_WAIT(0)        (own Wh(t) chunks landed)
//   __syncthreads()   (all Wh(t)+wts(t) visible; MMA(t-1) done everywhere)
//   prefetch Wh(t+1)  (overlaps MMA(t) and weights(t+1))
//   MMA(t): ldmatrix.x4 A/B + 32 mma
// ---------------------------------------------------------------------------
#define BSTRIDE 36                    // words per fragment row (72 halves)
#define WHT_WORDS (128 * BSTRIDE)     // 4608 per buffer
#define WTS_WORDS (64 * BSTRIDE)      // 2304 per buffer
#define SM_WHT 0                       // [2][WHT_WORDS]
#define SM_WTS (2 * WHT_WORDS)         // 9216, [2][WTS_WORDS]
#define SM_ZS  (SM_WTS + 2 * WTS_WORDS)  // 13824
#define SM_TOT (SM_ZS + 64)
#define SM_BYTES (SM_TOT * 4)          // 55552 B

__device__ __forceinline__ void mma_f16(float* d, const uint32_t* a,
                                        uint32_t b0, uint32_t b1) {
    asm volatile(
        "mma.sync.aligned.m16n8k16.row.col.f32.f16.f16.f32 "
        "{%0,%1,%2,%3}, {%4,%5,%6,%7}, {%8,%9}, {%0,%1,%2,%3};\n"
        : "+f"(d[0]), "+f"(d[1]), "+f"(d[2]), "+f"(d[3])
        : "r"(a[0]), "r"(a[1]), "r"(a[2]), "r"(a[3]), "r"(b0), "r"(b1));
}

__device__ __forceinline__ void ldsm4(uint32_t addr, uint32_t* r) {
    asm volatile("ldmatrix.sync.aligned.m8n8.x4.shared.b16 {%0,%1,%2,%3}, [%4];"
                 : "=r"(r[0]), "=r"(r[1]), "=r"(r[2]), "=r"(r[3]) : "r"(addr));
}

__device__ __forceinline__ void prefetch_wh(uint32_t* WhTs,
                                            const __half* WhTb,
                                            int buf, int j0, int t) {
    uint32_t* whDst = WhTs + buf * WHT_WORDS;
    #pragma unroll
    for (int p = 0; p < 4; p++) {
        int c = t + p * 256;            // chunk 0..1023
        int o = c >> 3, ch = c & 7;
        cp_async16(&whDst[o * BSTRIDE + ch * 4],
                   &WhTb[(size_t)o * NN + j0 + ch * 8]);
    }
    CP_COMMIT();
}

__global__ __launch_bounds__(256, 2) void k2_attn(
    const float* __restrict__ adj, float* __restrict__ out)
{
    extern __shared__ uint32_t smw[];
    uint32_t* WhTs = smw + SM_WHT;
    uint32_t* wts  = smw + SM_WTS;
    float* Zs = (float*)(smw + SM_ZS);

    const int t    = threadIdx.x;
    const int wid  = t >> 5;
    const int lane = t & 31;
    const int gid  = lane >> 2;
    const int tig  = lane & 3;
    const int b    = blockIdx.y;
    const int i0   = blockIdx.x * 64;

    const int m_warp = (wid & 1) * 32;      // 2 m-warps x 4 n-warps
    const int n_warp = (wid >> 1) * 32;

    const int wr  = t >> 2;          // weight row 0..63
    const int wc0 = (t & 3) * 16;    // weight col base

    if (t < 64) Zs[t] = 0.f;

    const float Efi = g_E1[(size_t)b * NN + i0 + wr];
    const float Gfi = g_G1[(size_t)b * NN + i0 + wr];
    const __half* WhTb = g_WhT + (size_t)b * OUTD * NN;
    const float* E2b = g_E2 + (size_t)b * NN;
    const float* G2b = g_G2 + (size_t)b * NN;
    const float* adjrow = adj + (size_t)(i0 + wr) * NN + wc0;

    // ldmatrix lane base addresses (shared-space byte offsets)
    const uint32_t smem0 = (uint32_t)__cvta_generic_to_shared(smw);
    const uint32_t aBase = smem0 + SM_WTS * 4 +
        (uint32_t)(((m_warp + (lane & 15)) * BSTRIDE + (lane >> 4) * 4) * 4);
    const uint32_t bBase = smem0 + SM_WHT * 4 +
        (uint32_t)(((n_warp + ((lane >> 4) & 1) * 8 + (lane & 7)) * BSTRIDE +
                    ((lane >> 3) & 1) * 4) * 4);

    // prologue: Wh tile 0
    prefetch_wh(WhTs, WhTb, 0, 0, t);

    float acc[2][4][4];
    #pragma unroll
    for (int u = 0; u < 2; u++)
        #pragma unroll
        for (int v = 0; v < 4; v++)
            #pragma unroll
            for (int j = 0; j < 4; j++) acc[u][v][j] = 0.f;

    float Zpart = 0.f;

    for (int tt = 0; tt < NN / 64; tt++) {
        const int idx = tt & 1;
        const int j0 = tt * 64;

        // ---- weight tile: direct LDG (L2-resident), fp16-rounded
        {
            uint32_t wb[8];
            #pragma unroll
            for (int q = 0; q < 4; q++) {
                float4 av = *(const float4*)&adjrow[j0 + q * 4];
                float4 ej = *(const float4*)&E2b[j0 + wc0 + q * 4];
                float4 gj = *(const float4*)&G2b[j0 + wc0 + q * 4];
                float w0 = fmaxf(Efi * ej.x, Gfi * gj.x) * av.x;
                float w1 = fmaxf(Efi * ej.y, Gfi * gj.y) * av.y;
                float w2 = fmaxf(Efi * ej.z, Gfi * gj.z) * av.z;
                float w3 = fmaxf(Efi * ej.w, Gfi * gj.w) * av.w;
                __half2 p0 = __floats2half2_rn(w0, w1);
                __half2 p1 = __floats2half2_rn(w2, w3);
                float2 r0 = __half22float2(p0);
                float2 r1 = __half22float2(p1);
                Zpart += (r0.x + r0.y) + (r1.x + r1.y);
                wb[q * 2]     = *(const uint32_t*)&p0;
                wb[q * 2 + 1] = *(const uint32_t*)&p1;
            }
            uint32_t* dst = &wts[idx * WTS_WORDS + wr * BSTRIDE + (t & 3) * 8];
            *(uint4*)dst       = make_uint4(wb[0], wb[1], wb[2], wb[3]);
            *(uint4*)(dst + 4) = make_uint4(wb[4], wb[5], wb[6], wb[7]);
        }

        CP_WAIT(0);               // own Wh(tt) chunks landed
        __syncthreads();          // the ONE barrier per tile

        if (tt + 1 < NN / 64)
            prefetch_wh(WhTs, WhTb, idx ^ 1, j0 + 64, t);

        // ---- MMA via ldmatrix: acc += wts(64x64) @ Wh(64x128)
        const uint32_t aT = aBase + (uint32_t)(idx * WTS_WORDS * 4);
        const uint32_t bT = bBase + (uint32_t)(idx * WHT_WORDS * 4);
        #pragma unroll
        for (int kw = 0; kw < 4; kw++) {
            uint32_t af[2][4], bf[2][4];
            ldsm4(aT + kw * 32,        af[0]);
            ldsm4(aT + 2304 + kw * 32, af[1]);   // +16 rows * 144 B
            ldsm4(bT + kw * 32,        bf[0]);   // n 0..15
            ldsm4(bT + 2304 + kw * 32, bf[1]);   // n 16..31
            #pragma unroll
            for (int u = 0; u < 2; u++) {
                mma_f16(acc[u][0], af[u], bf[0][0], bf[0][1]);
                mma_f16(acc[u][1], af[u], bf[0][2], bf[0][3]);
                mma_f16(acc[u][2], af[u], bf[1][0], bf[1][1]);
                mma_f16(acc[u][3], af[u], bf[1][2], bf[1][3]);
            }
        }
    }

    atomicAdd(&Zs[wr], Zpart);
    __syncthreads();

    // ---- epilogue: divide by Z, store
    #pragma unroll
    for (int u = 0; u < 2; u++) {
        const int row0e = m_warp + u * 16 + gid;
        const int row1e = row0e + 8;
        const float inv0 = 1.f / Zs[row0e];
        const float inv1 = 1.f / Zs[row1e];
        float* out0 = out + ((size_t)b * NN + i0 + row0e) * OUTD;
        float* out1 = out + ((size_t)b * NN + i0 + row1e) * OUTD;
        #pragma unroll
        for (int v = 0; v < 4; v++) {
            int col = n_warp + v * 8 + tig * 2;
            *(float2*)&out0[col] = make_float2(acc[u][v][0] * inv0,
                                               acc[u][v][1] * inv0);
            *(float2*)&out1[col] = make_float2(acc[u][v][2] * inv1,
                                               acc[u][v][3] * inv1);
        }
    }
}

// ---------------------------------------------------------------------------
extern "C" void kernel_launch(void* const* d_in, const int* in_sizes, int n_in,
                              void* d_out, int out_size)
{
    const float* h   = (const float*)d_in[0];   // (8, 2048, 256)
    const float* adj = (const float*)d_in[1];   // (2048, 2048)
    const float* W   = (const float*)d_in[2];   // (256, 128)
    const float* a   = (const float*)d_in[3];   // (256,)
    float* out = (float*)d_out;                 // (8, 2048, 128)

    k1_gemm_wh<<<ROWS / 64, 256>>>(h, W, a);

    cudaFuncSetAttribute(k2_attn, cudaFuncAttributeMaxDynamicSharedMemorySize,
                         SM_BYTES);
    k2_attn<<<dim3(NN / 64, BB), 256, SM_BYTES>>>(adj, out);
}